// round 16
// baseline (speedup 1.0000x reference)
#include <cuda_runtime.h>
#include <stdint.h>

#define BB    32
#define NBOX  8192
#define MGT   256
#define NP    8448        // NBOX + MGT
#define NSAMP 512
#define NFG   128
#define KBIN  256
#define KCAP  4096
#define LCAP  256
#define BCAP  2048
#define THRESH (1u << 20)            // keep negatives with inv_m < 2^20 (r > 0.875)
#define MASK37 ((1ull << 37) - 1)

// scratch (device globals -- no allocation allowed; zero-initialized at load;
// the last-CTA sample phase resets g_cnt/g_bandcnt/g_ticket -> replay safe)
__device__ unsigned long long g_sel[BB * KCAP];
__device__ unsigned int       g_cnt[BB];
__device__ unsigned int       g_bandcnt[BB * 8];
__device__ unsigned short     g_blist[BB * 8 * BCAP];
__device__ unsigned int       g_ticket[BB];

__device__ __forceinline__ uint32_t rotl32(uint32_t x, int d) {
    return (x << d) | (x >> (32 - d));
}

// JAX *partitionable* threefry, key = (0, 42). bits(p) = x0 ^ x1 of
// threefry2x32((0,42), (0, p))
__device__ __forceinline__ uint32_t threefry_bits(uint32_t p) {
    const uint32_t ks0 = 0u, ks1 = 42u, ks2 = 0x1BD11BF0u;  // 0x1BD11BDA ^ 0 ^ 42
    uint32_t x0 = 0u + ks0;
    uint32_t x1 = p + ks1;
#define TF_R(r) { x0 += x1; x1 = rotl32(x1, (r)); x1 ^= x0; }
    TF_R(13) TF_R(15) TF_R(26) TF_R(6)   x0 += ks1; x1 += ks2 + 1u;
    TF_R(17) TF_R(29) TF_R(16) TF_R(24)  x0 += ks2; x1 += ks0 + 2u;
    TF_R(13) TF_R(15) TF_R(26) TF_R(6)   x0 += ks0; x1 += ks1 + 3u;
    TF_R(17) TF_R(29) TF_R(16) TF_R(24)  x0 += ks1; x1 += ks2 + 4u;
    TF_R(13) TF_R(15) TF_R(26) TF_R(6)   x0 += ks2; x1 += ks0 + 5u;
#undef TF_R
    return x0 ^ x1;
}

// packed survivor word: [0:14) idx | [14:37) inv_m | bit37 pos | [38:46) mi
__device__ __forceinline__ void emit(int b, int i, bool pos, int mi) {
    uint32_t m = threefry_bits((uint32_t)(b * NP + i)) >> 9;
    uint32_t invm = 0x7FFFFFu - m;     // asc == r desc
    if (pos || invm < THRESH) {
        unsigned long long w = ((unsigned long long)(unsigned)mi << 38)
            | ((unsigned long long)(pos ? 1u : 0u) << 37)
            | ((unsigned long long)invm << 14) | (unsigned)i;
        unsigned j = atomicAdd(&g_cnt[b], 1u);
        if (j < KCAP) g_sel[b * KCAP + j] = w;
    }
}

// ---------------------------------------------------------------------------
// Kernel 0: bin boxes by y0 into 8 bands. 4 boxes/thread.
// grid (8 slices, 32 images) x 256 threads.
// ---------------------------------------------------------------------------
__global__ __launch_bounds__(256)
void roi_bin_kernel(const float* __restrict__ boxes) {
    __shared__ unsigned scnt[8], sbase[8];
    const int b = blockIdx.y;
    const int base = blockIdx.x * 1024 + threadIdx.x;
    if (threadIdx.x < 8) scnt[threadIdx.x] = 0u;
    __syncthreads();
    float y0[4]; int bd[4]; unsigned lofs[4];
#pragma unroll
    for (int k = 0; k < 4; ++k)
        y0[k] = __ldg(&boxes[(size_t)(b * NBOX + base + k * 256) * 4]);
#pragma unroll
    for (int k = 0; k < 4; ++k) {
        int d = (int)(y0[k] * 0.0078125f);   // exact: *2^-7, trunc
        bd[k] = d > 7 ? 7 : d;
        lofs[k] = atomicAdd(&scnt[bd[k]], 1u);
    }
    __syncthreads();
    if (threadIdx.x < 8)
        sbase[threadIdx.x] = atomicAdd(&g_bandcnt[b * 8 + threadIdx.x], scnt[threadIdx.x]);
    __syncthreads();
#pragma unroll
    for (int k = 0; k < 4; ++k) {
        unsigned pos = sbase[bd[k]] + lofs[k];
        if (pos < BCAP)
            g_blist[(b * 8 + bd[k]) * BCAP + pos] = (unsigned short)(base + k * 256);
    }
}

// ---------------------------------------------------------------------------
// Kernel 1 (fused): band-pruned max-IoU matching; the LAST finishing CTA of
// each image (ticket 16 of 17) continues into the selection+sort+gather
// phase (threadFenceReduction pattern -- no spin, no deadlock).
// grid (32, 17) x 256 threads.
// ---------------------------------------------------------------------------
__global__ __launch_bounds__(256)
void roi_match_kernel(const float* __restrict__ boxes,
                      const float* __restrict__ gt_boxes,
                      const int*   __restrict__ gt_classes,
                      float* __restrict__ out) {
    __shared__ float4 sg[MGT];
    __shared__ float  sga[MGT];
    __shared__ unsigned short gl[MGT];
    __shared__ unsigned wscan[8];
    __shared__ unsigned sh_ngl, sh_rank;
    // sample-phase smem (used only by the last CTA per image)
    __shared__ unsigned hP[KBIN], hN[KBIN], sPc[KBIN], sNc[KBIN];
    __shared__ unsigned wtP[8], wtN[8];
    __shared__ unsigned long long LP[LCAP], LN[LCAP], selk[NSAMP];
    __shared__ unsigned sh_bp, sh_bn, sh_befP, sh_befN;
    __shared__ unsigned cntP, cntN, cntS, sh_M;
    __shared__ unsigned long long sh_KP, sh_KN;

    const int b = blockIdx.x;
    const int y = blockIdx.y;
    const int t = threadIdx.x;
    const int T = 256;
    const int lane = t & 31, wid = t >> 5;

    float4 g4 = ((const float4*)gt_boxes)[b * MGT + t];
    float mx = fmaxf(fmaxf(g4.x, g4.y), fmaxf(g4.z, g4.w));
    bool valid = (mx >= 0.0f);
    sg[t] = g4;
    sga[t] = (g4.z - g4.x) * (g4.w - g4.y);
    const int nv = __syncthreads_count(valid);   // valid gts are a prefix

    if (y == 16) {
        // gt-candidates: full loop (tiny)
        float4 A = sg[t];
        const float abA = sga[t];
        float biA = -1.0f, buA = 1.0f; int miA = 0;
#pragma unroll 4
        for (int g = 0; g < nv; ++g) {
            float4 gb = sg[g];
            float ga  = sga[g];
            float dy = fminf(A.z, gb.z) - fmaxf(A.x, gb.x);
            float dx = fminf(A.w, gb.w) - fmaxf(A.y, gb.y);
            if (dy > 0.0f && dx > 0.0f) {
                float inter = dy * dx;
                float uni   = (abA + ga) - inter;
                if (inter * buA > biA * uni) { biA = inter; buA = uni; miA = g; }
            }
        }
        bool posA = (biA > 0.0f) && (__fdiv_rn(biA, buA) >= 0.5f);
        emit(b, NBOX + t, posA, miA);
    } else {
        const int band = y >> 1, slice = y & 1;
        const float blo = (float)(band * 128);
        const float bhi = blo + 264.0f;      // box y-extent within [blo, blo+264)

        // ascending-ordered compaction of candidate gts for this band
        bool memb = (t < nv) && (g4.z > blo) && (g4.x < bhi);
        unsigned mask = __ballot_sync(0xFFFFFFFFu, memb);
        if (lane == 0) wscan[wid] = __popc(mask);
        __syncthreads();
        if (t == 0) {
            unsigned s = 0;
            for (int i2 = 0; i2 < 8; ++i2) { unsigned c = wscan[i2]; wscan[i2] = s; s += c; }
            sh_ngl = s;
        }
        __syncthreads();
        if (memb) gl[wscan[wid] + __popc(mask & ((1u << lane) - 1u))] = (unsigned short)t;
        const int ngl = (int)sh_ngl;
        __syncthreads();

        unsigned cnt = g_bandcnt[b * 8 + band];
        cnt = (cnt < BCAP) ? cnt : BCAP;
        const unsigned half = (cnt + 1u) >> 1;
        const unsigned lob  = slice ? half : 0u;
        const unsigned end  = slice ? cnt : half;
        const unsigned short* list = &g_blist[(b * 8 + band) * BCAP];

        for (unsigned chunk = lob; chunk < end; chunk += 512u) {
            unsigned pA = chunk + (unsigned)t, pB = pA + 256u;
            bool vA = pA < end, vB = pB < end;
            int iA = vA ? (int)list[pA] : 0;
            int iB = vB ? (int)list[pB] : iA;
            float4 A  = ((const float4*)boxes)[b * NBOX + iA];
            float4 Bx = ((const float4*)boxes)[b * NBOX + iB];
            const float abA = (A.z - A.x) * (A.w - A.y);
            const float abB = (Bx.z - Bx.x) * (Bx.w - Bx.y);
            float biA = -1.0f, buA = 1.0f; int miA = 0;
            float biB = -1.0f, buB = 1.0f; int miB = 0;
#pragma unroll 4
            for (int g = 0; g < ngl; ++g) {
                int gid = (int)gl[g];            // uniform broadcast
                float4 gb = sg[gid];
                float ga  = sga[gid];
                {
                    float dy = fminf(A.z, gb.z) - fmaxf(A.x, gb.x);
                    float dx = fminf(A.w, gb.w) - fmaxf(A.y, gb.y);
                    if (dy > 0.0f && dx > 0.0f) {
                        float inter = dy * dx;
                        float uni   = (abA + ga) - inter;
                        if (inter * buA > biA * uni) { biA = inter; buA = uni; miA = gid; }
                    }
                }
                {
                    float dy = fminf(Bx.z, gb.z) - fmaxf(Bx.x, gb.x);
                    float dx = fminf(Bx.w, gb.w) - fmaxf(Bx.y, gb.y);
                    if (dy > 0.0f && dx > 0.0f) {
                        float inter = dy * dx;
                        float uni   = (abB + ga) - inter;
                        if (inter * buB > biB * uni) { biB = inter; buB = uni; miB = gid; }
                    }
                }
            }
            if (vA) {
                bool posA = (biA > 0.0f) && (__fdiv_rn(biA, buA) >= 0.5f);
                emit(b, iA, posA, miA);
            }
            if (vB) {
                bool posB = (biB > 0.0f) && (__fdiv_rn(biB, buB) >= 0.5f);
                emit(b, iB, posB, miB);
            }
        }
    }

    // ---- ticket: last CTA (of 17) for this image runs the sample phase ----
    __syncthreads();
    if (t == 0) {
        __threadfence();                         // release emits
        sh_rank = atomicAdd(&g_ticket[b], 1u);
    }
    __syncthreads();
    if (sh_rank != 16u) return;

    if (t == 0) {
        g_ticket[b] = 0u;                        // reset for next replay
        __threadfence();                         // acquire all producers' data
        cntP = 0; cntN = 0; cntS = 0; sh_KP = MASK37; sh_KN = MASK37;
        sh_M = atomicExch(&g_cnt[b], 0u);        // consume + reset
    }
    hP[t] = 0u; hN[t] = 0u;                      // T == KBIN == 256
    if (t < 8) g_bandcnt[b * 8 + t] = 0u;        // reset for next replay
    __syncthreads();
    const unsigned M = (sh_M < KCAP) ? sh_M : KCAP;
    const unsigned long long* sel = &g_sel[b * KCAP];

    // histogram on inv_m[22:15] (bits 29..36 of w); stream from L2
    for (unsigned p = t; p < M; p += T) {
        unsigned long long w = __ldcg(&sel[p]);
        unsigned bin = (unsigned)(w >> 29) & 0xFFu;
        if ((w >> 37) & 1ull) atomicAdd(&hP[bin], 1u);
        else                  atomicAdd(&hN[bin], 1u);
    }
    __syncthreads();

    // inclusive scan of 256 bins: warp shuffles + tiny cross-warp combine
    unsigned sP = hP[t], sN = hN[t];
#pragma unroll
    for (int off = 1; off < 32; off <<= 1) {
        unsigned vP = __shfl_up_sync(0xFFFFFFFFu, sP, off);
        unsigned vN = __shfl_up_sync(0xFFFFFFFFu, sN, off);
        if (lane >= off) { sP += vP; sN += vN; }
    }
    if (lane == 31) { wtP[wid] = sP; wtN[wid] = sN; }
    __syncthreads();
    {
        unsigned offP = 0, offN = 0;
        for (int ww = 0; ww < wid; ++ww) { offP += wtP[ww]; offN += wtN[ww]; }
        sPc[t] = sP + offP; sNc[t] = sN + offN;
    }
    __syncthreads();

    const unsigned total_pos = sPc[KBIN - 1];
    const unsigned n_pos = (total_pos < (unsigned)NFG) ? total_pos : (unsigned)NFG;
    const unsigned quota = (unsigned)NSAMP - n_pos;
    const bool needPsel = (total_pos > (unsigned)NFG);

    // boundary bins
    {
        unsigned iP = sPc[t], pP = t ? sPc[t - 1] : 0u;
        unsigned iN = sNc[t], pN = t ? sNc[t - 1] : 0u;
        if (needPsel && iP >= (unsigned)NFG && pP < (unsigned)NFG) { sh_bp = (unsigned)t; sh_befP = pP; }
        if (iN >= quota && pN < quota) { sh_bn = (unsigned)t; sh_befN = pN; }
    }
    __syncthreads();

    // collect boundary-bin items (masked 37-bit keys)
    {
        unsigned bp = needPsel ? sh_bp : 0xFFFFFFFFu;
        unsigned bn = sh_bn;
        for (unsigned p = t; p < M; p += T) {
            unsigned long long w = __ldcg(&sel[p]);
            unsigned bin = (unsigned)(w >> 29) & 0xFFu;
            if ((w >> 37) & 1ull) {
                if (bin == bp) { unsigned j = atomicAdd(&cntP, 1u); if (j < LCAP) LP[j] = w & MASK37; }
            } else {
                if (bin == bn) { unsigned j = atomicAdd(&cntN, 1u); if (j < LCAP) LN[j] = w & MASK37; }
            }
        }
    }
    selk[t] = ~0ull; selk[t + 256] = ~0ull;
    __syncthreads();

    // exact rank within boundary bins -> cutoff keys (keys are unique)
    {
        unsigned cp = cntP < LCAP ? cntP : LCAP;
        unsigned cn = cntN < LCAP ? cntN : LCAP;
        if (needPsel && (unsigned)t < cp) {
            unsigned long long k = LP[t]; unsigned r = 0;
            for (unsigned l = 0; l < cp; ++l) r += (LP[l] < k);
            if (r == ((unsigned)NFG - sh_befP) - 1u) sh_KP = k;
        }
        if ((unsigned)t < cn) {
            unsigned long long k = LN[t]; unsigned r = 0;
            for (unsigned l = 0; l < cn; ++l) r += (LN[l] < k);
            if (r == (quota - sh_befN) - 1u) sh_KN = k;
        }
    }
    __syncthreads();

    // final selection (exactly 512); re-key by RNE-rounded score mantissa.
    // score = 2.0f + r rounds r's 23-bit mantissa m to 2^-22 grid:
    //   h = (m>>1) + ((m&1) & ((m>>1)&1)); ties broken by idx asc.
    {
        unsigned long long KP = sh_KP, KN = sh_KN;
        for (unsigned p = t; p < M; p += T) {
            unsigned long long w = __ldcg(&sel[p]);
            unsigned long long kk = w & MASK37;
            bool selb = ((w >> 37) & 1ull) ? (kk <= KP) : (kk <= KN);
            if (selb) {
                unsigned mm = 0x7FFFFFu - (unsigned)((w >> 14) & 0x7FFFFFu);
                unsigned h  = (mm >> 1) + ((mm & 1u) & ((mm >> 1) & 1u));
                unsigned j  = atomicAdd(&cntS, 1u);
                selk[j] = (w & ~MASK37)                        // keep pos|mi high bits
                        | (((unsigned long long)(0x7FFFFFu - h)) << 14)
                        | (w & 0x3FFFull);
            }
        }
    }
    __syncthreads();

    // bitonic sort 512 keys by low 37 bits asc (== score desc, idx asc);
    // 256 threads, strided 2 elements/thread (round-3-proven pattern).
    for (unsigned k = 2; k <= (unsigned)NSAMP; k <<= 1) {
        for (unsigned j = k >> 1; j > 0; j >>= 1) {
            for (unsigned p = (unsigned)t; p < (unsigned)NSAMP; p += (unsigned)T) {
                unsigned q = p ^ j;
                if (q > p) {
                    unsigned long long a = selk[p], c = selk[q];
                    bool up = ((p & k) == 0);
                    if (((a << 27) > (c << 27)) == up) { selk[p] = c; selk[q] = a; }
                }
            }
            __syncthreads();
        }
    }

    // gather outputs (2 slots/thread)
    for (unsigned p = (unsigned)t; p < (unsigned)NSAMP; p += (unsigned)T) {
        unsigned long long v = selk[p];
        if (p < cntS) {
            unsigned i  = (unsigned)(v & 0x3FFFu);
            bool pos    = (v >> 37) & 1ull;
            int  mi     = (int)((v >> 38) & 0xFFull);
            float4 roi = (i < NBOX)
                ? ((const float4*)boxes)[b * NBOX + i]
                : ((const float4*)gt_boxes)[b * MGT + (i - NBOX)];
            float4 gb = make_float4(0.f, 0.f, 0.f, 0.f);
            float cls = 0.0f, gidx = -1.0f;
            if (pos) {
                gb   = ((const float4*)gt_boxes)[b * MGT + mi];
                cls  = (float)gt_classes[b * MGT + mi];
                gidx = (float)mi;
            }
            size_t base = (size_t)(b * NSAMP + p);
            float* o1 = out + base * 4;                                   // rois
            o1[0] = roi.x; o1[1] = roi.y; o1[2] = roi.z; o1[3] = roi.w;
            float* o2 = out + (size_t)BB * NSAMP * 4 + base * 4;          // matched gt boxes
            o2[0] = gb.x; o2[1] = gb.y; o2[2] = gb.z; o2[3] = gb.w;
            out[(size_t)2 * BB * NSAMP * 4 + base] = cls;                 // classes
            out[(size_t)2 * BB * NSAMP * 4 + (size_t)BB * NSAMP + base] = gidx; // indices
        }
    }
}

extern "C" void kernel_launch(void* const* d_in, const int* in_sizes, int n_in,
                              void* d_out, int out_size) {
    (void)out_size;
    const float* boxes      = (const float*)d_in[0];
    const float* gt_boxes   = (const float*)d_in[1];
    const int*   gt_classes = (const int*)d_in[2];
    for (int k = 0; k < n_in; ++k) {
        if (in_sizes[k] == BB * NBOX * 4) boxes      = (const float*)d_in[k];
        else if (in_sizes[k] == BB * MGT * 4) gt_boxes = (const float*)d_in[k];
        else if (in_sizes[k] == BB * MGT)     gt_classes = (const int*)d_in[k];
    }
    float* out = (float*)d_out;

    dim3 g0(8, BB);
    roi_bin_kernel<<<g0, 256>>>(boxes);

    dim3 g1(BB, 17);
    roi_match_kernel<<<g1, 256>>>(boxes, gt_boxes, gt_classes, out);
}

// round 17
// speedup vs baseline: 1.2731x; 1.2731x over previous
#include <cuda_runtime.h>
#include <stdint.h>

#define BB    32
#define NBOX  8192
#define MGT   256
#define NP    8448        // NBOX + MGT
#define NSAMP 512
#define NFG   128
#define KBIN  256
#define KCAP  4096
#define LCAP  256
#define CCAP  512
#define THRESH (1u << 20)            // keep negatives with inv_m < 2^20 (r > 0.875)
#define MASK37 ((1ull << 37) - 1)

// scratch (device globals -- no allocation allowed; zero-initialized at load;
// k2 resets g_cnt/g_cellcnt each run -> graph-replay safe)
__device__ unsigned long long g_sel[BB * KCAP];
__device__ unsigned int       g_cnt[BB];
__device__ unsigned int       g_cellcnt[BB * 64];
__device__ unsigned short     g_clist[BB * 64 * CCAP];

__device__ __forceinline__ uint32_t rotl32(uint32_t x, int d) {
    return (x << d) | (x >> (32 - d));
}

// JAX *partitionable* threefry, key = (0, 42). bits(p) = x0 ^ x1 of
// threefry2x32((0,42), (0, p))
__device__ __forceinline__ uint32_t threefry_bits(uint32_t p) {
    const uint32_t ks0 = 0u, ks1 = 42u, ks2 = 0x1BD11BF0u;  // 0x1BD11BDA ^ 0 ^ 42
    uint32_t x0 = 0u + ks0;
    uint32_t x1 = p + ks1;
#define TF_R(r) { x0 += x1; x1 = rotl32(x1, (r)); x1 ^= x0; }
    TF_R(13) TF_R(15) TF_R(26) TF_R(6)   x0 += ks1; x1 += ks2 + 1u;
    TF_R(17) TF_R(29) TF_R(16) TF_R(24)  x0 += ks2; x1 += ks0 + 2u;
    TF_R(13) TF_R(15) TF_R(26) TF_R(6)   x0 += ks0; x1 += ks1 + 3u;
    TF_R(17) TF_R(29) TF_R(16) TF_R(24)  x0 += ks1; x1 += ks2 + 4u;
    TF_R(13) TF_R(15) TF_R(26) TF_R(6)   x0 += ks2; x1 += ks0 + 5u;
#undef TF_R
    return x0 ^ x1;
}

// packed survivor word: [0:14) idx | [14:37) inv_m | bit37 pos | [38:46) mi
__device__ __forceinline__ void emit(int b, int i, bool pos, int mi) {
    uint32_t m = threefry_bits((uint32_t)(b * NP + i)) >> 9;
    uint32_t invm = 0x7FFFFFu - m;     // asc == r desc
    if (pos || invm < THRESH) {
        unsigned long long w = ((unsigned long long)(unsigned)mi << 38)
            | ((unsigned long long)(pos ? 1u : 0u) << 37)
            | ((unsigned long long)invm << 14) | (unsigned)i;
        unsigned j = atomicAdd(&g_cnt[b], 1u);
        if (j < KCAP) g_sel[b * KCAP + j] = w;
    }
}

// ---------------------------------------------------------------------------
// Kernel 0: bin boxes into an 8x8 cell grid by (y0>>7, x0>>7). 4 boxes/thread.
// grid (8 slices, 32 images) x 256 threads. Box layout: [y0, x0, y1, x1].
// ---------------------------------------------------------------------------
__global__ __launch_bounds__(256)
void roi_bin_kernel(const float* __restrict__ boxes) {
    __shared__ unsigned scnt[64], sbase[64];
    const int b = blockIdx.y;
    const int base = blockIdx.x * 1024 + threadIdx.x;
    if (threadIdx.x < 64) scnt[threadIdx.x] = 0u;
    __syncthreads();
    float2 yx[4]; int cd[4]; unsigned lofs[4];
#pragma unroll
    for (int k = 0; k < 4; ++k)
        yx[k] = ((const float2*)boxes)[(size_t)(b * NBOX + base + k * 256) * 2];
#pragma unroll
    for (int k = 0; k < 4; ++k) {
        int cy = (int)(yx[k].x * 0.0078125f);   // exact: *2^-7, trunc; y0 < 1024
        int cx = (int)(yx[k].y * 0.0078125f);
        cy = cy > 7 ? 7 : cy; cx = cx > 7 ? 7 : cx;
        cd[k] = cy * 8 + cx;
        lofs[k] = atomicAdd(&scnt[cd[k]], 1u);
    }
    __syncthreads();
    if (threadIdx.x < 64)
        sbase[threadIdx.x] = atomicAdd(&g_cellcnt[b * 64 + threadIdx.x], scnt[threadIdx.x]);
    __syncthreads();
#pragma unroll
    for (int k = 0; k < 4; ++k) {
        unsigned pos = sbase[cd[k]] + lofs[k];
        if (pos < CCAP)
            g_clist[(b * 64 + cd[k]) * CCAP + pos] = (unsigned short)(base + k * 256);
    }
}

// ---------------------------------------------------------------------------
// Kernel 1: max-IoU matching over 2D-cell-pruned gt candidate lists.
// grid (32, 65): y<64 -> cell (cy = y>>3, cx = y&7); y==64 -> 256
// gt-candidates (full loop). Guarded update (frozen round-8 form).
// Candidate list: ascending exact superset per-dim -> bit-identical argmax.
// ---------------------------------------------------------------------------
__global__ __launch_bounds__(256)
void roi_match_kernel(const float* __restrict__ boxes,
                      const float* __restrict__ gt_boxes) {
    __shared__ float4 sg[MGT];
    __shared__ float  sga[MGT];
    __shared__ unsigned short gl[MGT];
    __shared__ unsigned wscan[8];
    __shared__ unsigned sh_ngl;

    const int b = blockIdx.x;
    const int y = blockIdx.y;
    const int t = threadIdx.x;
    const int lane = t & 31, wid = t >> 5;

    float4 g4 = ((const float4*)gt_boxes)[b * MGT + t];
    float mx = fmaxf(fmaxf(g4.x, g4.y), fmaxf(g4.z, g4.w));
    bool valid = (mx >= 0.0f);
    sg[t] = g4;
    sga[t] = (g4.z - g4.x) * (g4.w - g4.y);
    const int nv = __syncthreads_count(valid);   // valid gts are a prefix

    if (y == 64) {
        // gt-candidates: full loop (tiny)
        float4 A = sg[t];
        const float abA = sga[t];
        float biA = -1.0f, buA = 1.0f; int miA = 0;
#pragma unroll 4
        for (int g = 0; g < nv; ++g) {
            float4 gb = sg[g];
            float ga  = sga[g];
            float dy = fminf(A.z, gb.z) - fmaxf(A.x, gb.x);
            float dx = fminf(A.w, gb.w) - fmaxf(A.y, gb.y);
            if (dy > 0.0f && dx > 0.0f) {
                float inter = dy * dx;
                float uni   = (abA + ga) - inter;
                if (inter * buA > biA * uni) { biA = inter; buA = uni; miA = g; }
            }
        }
        bool posA = (biA > 0.0f) && (__fdiv_rn(biA, buA) >= 0.5f);
        emit(b, NBOX + t, posA, miA);
        return;
    }

    const int cy = y >> 3, cx = y & 7;
    const float ylo = (float)(cy * 128), yhi = ylo + 264.0f;
    const float xlo = (float)(cx * 128), xhi = xlo + 264.0f;

    // ascending-ordered compaction of candidate gts for this cell
    bool memb = (t < nv) && (g4.z > ylo) && (g4.x < yhi)
                         && (g4.w > xlo) && (g4.y < xhi);
    unsigned mask = __ballot_sync(0xFFFFFFFFu, memb);
    if (lane == 0) wscan[wid] = __popc(mask);
    __syncthreads();
    if (t == 0) {
        unsigned s = 0;
        for (int i2 = 0; i2 < 8; ++i2) { unsigned c = wscan[i2]; wscan[i2] = s; s += c; }
        sh_ngl = s;
    }
    __syncthreads();
    if (memb) gl[wscan[wid] + __popc(mask & ((1u << lane) - 1u))] = (unsigned short)t;
    const int ngl = (int)sh_ngl;
    __syncthreads();

    unsigned cnt = g_cellcnt[b * 64 + y];
    cnt = (cnt < CCAP) ? cnt : CCAP;
    const unsigned short* list = &g_clist[(b * 64 + y) * CCAP];

    for (unsigned p = (unsigned)t; p < cnt; p += 256u) {
        int i = (int)list[p];
        float4 A = ((const float4*)boxes)[b * NBOX + i];
        const float abA = (A.z - A.x) * (A.w - A.y);
        // bi=-1 sentinel: first overlapping gt always wins; bi>0 <=> overlap
        float biA = -1.0f, buA = 1.0f; int miA = 0;
#pragma unroll 4
        for (int g = 0; g < ngl; ++g) {
            int gid = (int)gl[g];                // uniform broadcast
            float4 gb = sg[gid];
            float ga  = sga[gid];
            float dy = fminf(A.z, gb.z) - fmaxf(A.x, gb.x);
            float dx = fminf(A.w, gb.w) - fmaxf(A.y, gb.y);
            if (dy > 0.0f && dx > 0.0f) {
                float inter = dy * dx;
                float uni   = (abA + ga) - inter;
                if (inter * buA > biA * uni) { biA = inter; buA = uni; miA = gid; }
            }
        }
        bool posA = (biA > 0.0f) && (__fdiv_rn(biA, buA) >= 0.5f);
        emit(b, i, posA, miA);
    }
}

// ---------------------------------------------------------------------------
// Kernel 2: per-image select over compacted survivors + 512-sort + gather.
// (round-11/13/15 version, verbatim; resets g_cnt/g_cellcnt) 32 CTAs x 512.
// ---------------------------------------------------------------------------
__global__ __launch_bounds__(512)
void roi_sample_kernel(const float* __restrict__ boxes,
                       const float* __restrict__ gt_boxes,
                       const int*   __restrict__ gt_classes,
                       float* __restrict__ out) {
    extern __shared__ unsigned long long items[];   // KCAP
    __shared__ unsigned hP[KBIN], hN[KBIN], sPc[KBIN], sNc[KBIN];
    __shared__ unsigned wtP[8], wtN[8];
    __shared__ unsigned long long LP[LCAP], LN[LCAP], selk[NSAMP];
    __shared__ unsigned sh_bp, sh_bn, sh_befP, sh_befN;
    __shared__ unsigned cntP, cntN, cntS;
    __shared__ unsigned long long sh_KP, sh_KN;

    const int b = blockIdx.x;
    const int t = threadIdx.x;
    const int T = 512;
    const int lane = t & 31, wid = t >> 5;

    if (t == 0) { cntP = 0; cntN = 0; cntS = 0; sh_KP = MASK37; sh_KN = MASK37; }
    if (t < KBIN) { hP[t] = 0u; hN[t] = 0u; }
    const unsigned M0 = g_cnt[b];
    const unsigned M = (M0 < KCAP) ? M0 : KCAP;
    __syncthreads();
    if (t == 0) g_cnt[b] = 0u;          // reset for next replay
    if (t >= 64 && t < 128) g_cellcnt[b * 64 + (t - 64)] = 0u;

    // load survivors + histogram on inv_m[22:15]  (bits 29..36 of w)
    for (unsigned p = t; p < M; p += T) {
        unsigned long long w = g_sel[b * KCAP + p];
        items[p] = w;
        unsigned bin = (unsigned)(w >> 29) & 0xFFu;
        if ((w >> 37) & 1ull) atomicAdd(&hP[bin], 1u);
        else                  atomicAdd(&hN[bin], 1u);
    }
    __syncthreads();

    // inclusive scan of 256 bins: warp shuffles + tiny cross-warp combine
    unsigned sP = 0, sN = 0;
    if (t < KBIN) {
        sP = hP[t]; sN = hN[t];
#pragma unroll
        for (int off = 1; off < 32; off <<= 1) {
            unsigned vP = __shfl_up_sync(0xFFFFFFFFu, sP, off);
            unsigned vN = __shfl_up_sync(0xFFFFFFFFu, sN, off);
            if (lane >= off) { sP += vP; sN += vN; }
        }
        if (lane == 31) { wtP[wid] = sP; wtN[wid] = sN; }
    }
    __syncthreads();
    if (t < KBIN) {
        unsigned offP = 0, offN = 0;
        for (int ww = 0; ww < wid; ++ww) { offP += wtP[ww]; offN += wtN[ww]; }
        sPc[t] = sP + offP; sNc[t] = sN + offN;
    }
    __syncthreads();

    const unsigned total_pos = sPc[KBIN - 1];
    const unsigned n_pos = (total_pos < (unsigned)NFG) ? total_pos : (unsigned)NFG;
    const unsigned quota = (unsigned)NSAMP - n_pos;
    const bool needPsel = (total_pos > (unsigned)NFG);

    // boundary bins
    if (t < KBIN) {
        unsigned iP = sPc[t], pP = t ? sPc[t - 1] : 0u;
        unsigned iN = sNc[t], pN = t ? sNc[t - 1] : 0u;
        if (needPsel && iP >= (unsigned)NFG && pP < (unsigned)NFG) { sh_bp = (unsigned)t; sh_befP = pP; }
        if (iN >= quota && pN < quota) { sh_bn = (unsigned)t; sh_befN = pN; }
    }
    __syncthreads();

    // collect boundary-bin items (masked 37-bit keys)
    {
        unsigned bp = needPsel ? sh_bp : 0xFFFFFFFFu;
        unsigned bn = sh_bn;
        for (unsigned p = t; p < M; p += T) {
            unsigned long long w = items[p];
            unsigned bin = (unsigned)(w >> 29) & 0xFFu;
            if ((w >> 37) & 1ull) {
                if (bin == bp) { unsigned j = atomicAdd(&cntP, 1u); if (j < LCAP) LP[j] = w & MASK37; }
            } else {
                if (bin == bn) { unsigned j = atomicAdd(&cntN, 1u); if (j < LCAP) LN[j] = w & MASK37; }
            }
        }
    }
    selk[t] = ~0ull;
    __syncthreads();

    // exact rank within boundary bins -> cutoff keys (keys are unique)
    {
        unsigned cp = cntP < LCAP ? cntP : LCAP;
        unsigned cn = cntN < LCAP ? cntN : LCAP;
        if (needPsel && (unsigned)t < cp) {
            unsigned long long k = LP[t]; unsigned r = 0;
            for (unsigned l = 0; l < cp; ++l) r += (LP[l] < k);
            if (r == ((unsigned)NFG - sh_befP) - 1u) sh_KP = k;
        }
        if ((unsigned)t < cn) {
            unsigned long long k = LN[t]; unsigned r = 0;
            for (unsigned l = 0; l < cn; ++l) r += (LN[l] < k);
            if (r == (quota - sh_befN) - 1u) sh_KN = k;
        }
    }
    __syncthreads();

    // final selection (exactly 512); re-key by RNE-rounded score mantissa.
    // score = 2.0f + r rounds r's 23-bit mantissa m to 2^-22 grid:
    //   h = (m>>1) + ((m&1) & ((m>>1)&1)); ties broken by idx asc.
    {
        unsigned long long KP = sh_KP, KN = sh_KN;
        for (unsigned p = t; p < M; p += T) {
            unsigned long long w = items[p];
            unsigned long long kk = w & MASK37;
            bool sel = ((w >> 37) & 1ull) ? (kk <= KP) : (kk <= KN);
            if (sel) {
                unsigned mm = 0x7FFFFFu - (unsigned)((w >> 14) & 0x7FFFFFu);
                unsigned h  = (mm >> 1) + ((mm & 1u) & ((mm >> 1) & 1u));
                unsigned j  = atomicAdd(&cntS, 1u);
                selk[j] = (w & ~MASK37)                        // keep pos|mi high bits
                        | (((unsigned long long)(0x7FFFFFu - h)) << 14)
                        | (w & 0x3FFFull);
            }
        }
    }
    __syncthreads();

    // bitonic sort 512 keys by low 37 bits asc (== score desc, idx asc);
    // pos/mi ride in the high bits, masked out of comparisons via <<27.
    for (unsigned k = 2; k <= (unsigned)NSAMP; k <<= 1) {
        for (unsigned j = k >> 1; j > 0; j >>= 1) {
            unsigned p = (unsigned)t, q = p ^ j;
            if (q > p) {
                unsigned long long a = selk[p], c = selk[q];
                bool up = ((p & k) == 0);
                if (((a << 27) > (c << 27)) == up) { selk[p] = c; selk[q] = a; }
            }
            __syncthreads();
        }
    }

    // gather outputs
    {
        unsigned long long v = selk[t];
        if ((unsigned)t < cntS) {
            unsigned i  = (unsigned)(v & 0x3FFFu);
            bool pos    = (v >> 37) & 1ull;
            int  mi     = (int)((v >> 38) & 0xFFull);
            float4 roi = (i < NBOX)
                ? ((const float4*)boxes)[b * NBOX + i]
                : ((const float4*)gt_boxes)[b * MGT + (i - NBOX)];
            float4 gb = make_float4(0.f, 0.f, 0.f, 0.f);
            float cls = 0.0f, gidx = -1.0f;
            if (pos) {
                gb   = ((const float4*)gt_boxes)[b * MGT + mi];
                cls  = (float)gt_classes[b * MGT + mi];
                gidx = (float)mi;
            }
            size_t base = (size_t)(b * NSAMP + t);
            float* o1 = out + base * 4;                                   // rois
            o1[0] = roi.x; o1[1] = roi.y; o1[2] = roi.z; o1[3] = roi.w;
            float* o2 = out + (size_t)BB * NSAMP * 4 + base * 4;          // matched gt boxes
            o2[0] = gb.x; o2[1] = gb.y; o2[2] = gb.z; o2[3] = gb.w;
            out[(size_t)2 * BB * NSAMP * 4 + base] = cls;                 // classes
            out[(size_t)2 * BB * NSAMP * 4 + (size_t)BB * NSAMP + base] = gidx; // indices
        }
    }
}

extern "C" void kernel_launch(void* const* d_in, const int* in_sizes, int n_in,
                              void* d_out, int out_size) {
    (void)out_size;
    const float* boxes      = (const float*)d_in[0];
    const float* gt_boxes   = (const float*)d_in[1];
    const int*   gt_classes = (const int*)d_in[2];
    for (int k = 0; k < n_in; ++k) {
        if (in_sizes[k] == BB * NBOX * 4) boxes      = (const float*)d_in[k];
        else if (in_sizes[k] == BB * MGT * 4) gt_boxes = (const float*)d_in[k];
        else if (in_sizes[k] == BB * MGT)     gt_classes = (const int*)d_in[k];
    }
    float* out = (float*)d_out;

    dim3 g0(8, BB);
    roi_bin_kernel<<<g0, 256>>>(boxes);

    dim3 g1(BB, 65);
    roi_match_kernel<<<g1, 256>>>(boxes, gt_boxes);

    size_t smem = (size_t)KCAP * 8;   // 32 KB dynamic (items)
    cudaFuncSetAttribute(roi_sample_kernel,
                         cudaFuncAttributeMaxDynamicSharedMemorySize, (int)smem);
    roi_sample_kernel<<<BB, 512, smem>>>(boxes, gt_boxes, gt_classes, out);
}